// round 16
// baseline (speedup 1.0000x reference)
#include <cuda_runtime.h>
#include <cuda_fp16.h>
#include <cstdint>
#include <cstddef>

// ---------------------------------------------------------------------------
// mulGCN: two-branch GCN forward, fp16 mma.sync GEMMs + 4-stage cp.async
// pipeline, all node intermediates packed fp16.
// R16: consolidated schedule — branch-combined launches (grid.z=2 GEMMs,
// combined gather/segsum, fused conv) on 2 streams with 3 events:
//   s0: conv_all (evNF) -> G0both -> [wait evG] -> G1both -> G2both
//       -> segsum_both -> readout
//   s2: CSR chain -> [wait evNF] -> gather_both (evG)
// Math: t2 = h@Wr; h1 = relu(hagg@W+b)+relu(t2+br); h2 = relu(h1@Ri+rbi);
// T[g] = segsum h2; out = (T1@Ro1 + c1*rbo1 + T2@Ro2 + c2*rbo2) . Wp + bp
// ---------------------------------------------------------------------------

#define N_NODES   50000
#define N_EDGES   800000
#define DFEAT     256
#define G_FEAT    200
#define N_GRAPHS  512

#define NW   (N_NODES * 128)          // fp16-pair words per branch

#define SCAN_BLKS   49
#define SCAN_CHUNK  1024

__device__ uint32_t g_t2Q [2][(size_t)NW];   // h@Wr fp16; reused as h2
__device__ uint32_t g_aggQ[2][(size_t)NW];
__device__ uint32_t g_nfQ [2][(size_t)NW];
__device__ uint32_t g_h1Q [2][(size_t)NW];
__device__ uint32_t g_WQ  [6][128 * 256];   // k-major pairs: [kp][n]
__device__ float    g_T   [2][N_GRAPHS * DFEAT];
__device__ int      g_counts  [2][N_GRAPHS];
__device__ int      g_deg     [2][N_NODES];
__device__ int      g_rowstart[2][N_NODES + 1];
__device__ int      g_cursor  [2][N_NODES];
__device__ int      g_csr_src [2][N_EDGES];
__device__ int      g_bsums   [2 * SCAN_BLKS];

__device__ __forceinline__ float frelu(float x) { return x > 0.f ? x : 0.f; }

// ------------------------- mma / pack helpers ------------------------------
__device__ __forceinline__ void mma16816(float* c, const uint32_t* a,
                                         uint32_t b0, uint32_t b1) {
    asm volatile(
        "mma.sync.aligned.m16n8k16.row.col.f32.f16.f16.f32 "
        "{%0,%1,%2,%3}, {%4,%5,%6,%7}, {%8,%9}, {%0,%1,%2,%3};\n"
        : "+f"(c[0]), "+f"(c[1]), "+f"(c[2]), "+f"(c[3])
        : "r"(a[0]), "r"(a[1]), "r"(a[2]), "r"(a[3]), "r"(b0), "r"(b1));
}

__device__ __forceinline__ uint32_t pack_f16(float x, float y) {
    __half2 t;
    t.x = __float2half_rn(x);
    t.y = __float2half_rn(y);
    return *reinterpret_cast<uint32_t*>(&t);
}
__device__ __forceinline__ float2 unpack_f16(uint32_t w) {
    return __half22float2(*reinterpret_cast<__half2*>(&w));
}

// ------------------------- cp.async helpers --------------------------------
__device__ __forceinline__ void cp16(uint32_t dst, const void* src) {
    asm volatile("cp.async.cg.shared.global [%0], [%1], 16;"
                 :: "r"(dst), "l"(src));
}
__device__ __forceinline__ void cp16z(uint32_t dst, const void* src, bool ok) {
    int b = ok ? 16 : 0;
    asm volatile("cp.async.cg.shared.global [%0], [%1], 16, %2;"
                 :: "r"(dst), "l"(src), "r"(b));
}
#define CP_COMMIT()  asm volatile("cp.async.commit_group;" ::: "memory")
#define CP_WAIT(n)   asm volatile("cp.async.wait_group %0;" :: "n"(n) : "memory")

// SMEM words per buffer: A[128][20]  B[16][136]; 4 buffers
static constexpr int W_A = 0, W_B = 2560;
static constexpr int WBUF = 4736;
static constexpr int N_STAGE = 4;
static constexpr int SMEM_BYTES = N_STAGE * WBUF * 4;   // 75776

__device__ __forceinline__ void cpA(uint32_t sb, const uint32_t* __restrict__ A,
                                    int M, int rowBase, int c, int tid)
{
    #pragma unroll
    for (int t = 0; t < 2; t++) {
        int idx = tid + t * 256;          // 0..511
        int r   = idx >> 2;
        int s4  = (idx & 3) * 4;
        int row = rowBase + r;
        bool ok = row < M;
        int rowc = ok ? row : 0;
        const uint32_t* src = A + (size_t)rowc * 128 + c * 16 + s4;
        uint32_t dst = sb + (W_A + r * 20 + s4) * 4;
        cp16z(dst, src, ok);
    }
}

__device__ __forceinline__ void cpB(uint32_t sb, const uint32_t* __restrict__ Wq,
                                    int colBase, int c, int tid)
{
    #pragma unroll
    for (int t = 0; t < 2; t++) {
        int idx = tid + t * 256;          // 0..511
        int kp  = idx >> 5;               // 0..15
        int n4  = (idx & 31) * 4;         // 0..124
        const uint32_t* src = Wq + (size_t)(c * 16 + kp) * 256 + colBase + n4;
        uint32_t dst = sb + (W_B + kp * 136 + n4) * 4;
        cp16(dst, src);
    }
}

// ---------------------------------------------------------------------------
// fp16 mma GEMM, both branches (grid.z): 256 threads, 8 warps (4m x 2n),
// warp 32x64, 4-stage pipeline. All outputs packed fp16.
// MODE 0: CQ = pack(acc)
// MODE 1: CQ = pack(relu(acc+bias) + relu(unpack(aggQ)+bagg))
// MODE 2: CQ = pack(relu(acc+bias))
// ---------------------------------------------------------------------------
template<int MODE>
__global__ __launch_bounds__(256, 2)
void gemm_mma(const uint32_t* __restrict__ A1, const uint32_t* __restrict__ A2,
              const uint32_t* __restrict__ Wq1, const uint32_t* __restrict__ Wq2,
              const float* __restrict__ bias1, const float* __restrict__ bias2,
              const uint32_t* __restrict__ aggQ1, const uint32_t* __restrict__ aggQ2,
              const float* __restrict__ bagg1, const float* __restrict__ bagg2,
              uint32_t* __restrict__ CQ1, uint32_t* __restrict__ CQ2,
              int M)
{
    extern __shared__ uint32_t sm[];
    const int br = blockIdx.z;
    const uint32_t* A    = br ? A2 : A1;
    const uint32_t* Wq   = br ? Wq2 : Wq1;
    const float* bias    = br ? bias2 : bias1;
    const uint32_t* aggQ = br ? aggQ2 : aggQ1;
    const float* bagg    = br ? bagg2 : bagg1;
    uint32_t* CQ         = br ? CQ2 : CQ1;

    const int tid  = threadIdx.x;
    const int lane = tid & 31;
    const int wid  = tid >> 5;
    const int wm   = wid & 3;
    const int wn   = wid >> 2;
    const int gid  = lane >> 2;
    const int tig  = lane & 3;
    const int rowBase = blockIdx.x * 128;
    const int colBase = blockIdx.y * 128;

    uint32_t sbase;
    {
        uint64_t a = __cvta_generic_to_shared(sm);
        sbase = (uint32_t)a;
    }

    float acc[2][8][4];
    #pragma unroll
    for (int mt = 0; mt < 2; mt++)
        #pragma unroll
        for (int nt = 0; nt < 8; nt++)
            #pragma unroll
            for (int q = 0; q < 4; q++) acc[mt][nt][q] = 0.f;

    #pragma unroll
    for (int p = 0; p < 3; p++) {
        uint32_t pb = sbase + p * (WBUF * 4);
        cpA(pb, A, M, rowBase, p, tid);
        cpB(pb, Wq, colBase, p, tid);
        CP_COMMIT();
    }

    #pragma unroll
    for (int c = 0; c < 8; c++) {
        if (c < 5) {
            uint32_t nb = sbase + ((c + 3) & 3) * (WBUF * 4);
            cpA(nb, A, M, rowBase, c + 3, tid);
            cpB(nb, Wq, colBase, c + 3, tid);
            CP_COMMIT();
        }
        if (c < 5)       CP_WAIT(3);
        else if (c == 5) CP_WAIT(2);
        else if (c == 6) CP_WAIT(1);
        else             CP_WAIT(0);
        __syncthreads();

        const uint32_t* buf = sm + (c & 3) * WBUF;
        const uint32_t* sA = buf + W_A;
        const uint32_t* sB = buf + W_B;

        #pragma unroll
        for (int ks = 0; ks < 2; ks++) {
            uint32_t a[2][4];
            #pragma unroll
            for (int mt = 0; mt < 2; mt++) {
                int off = (wm * 32 + mt * 16 + gid) * 20 + ks * 8 + tig;
                a[mt][0] = sA[off];       a[mt][1] = sA[off + 160];
                a[mt][2] = sA[off + 4];   a[mt][3] = sA[off + 164];
            }
            #pragma unroll
            for (int nt = 0; nt < 8; nt++) {
                int bi = (ks * 8 + tig) * 136 + wn * 64 + nt * 8 + gid;
                uint32_t b0 = sB[bi], b1 = sB[bi + 544];
                #pragma unroll
                for (int mt = 0; mt < 2; mt++)
                    mma16816(acc[mt][nt], a[mt], b0, b1);
            }
        }
        __syncthreads();
    }

    // ------------------------------ epilogue -------------------------------
    #pragma unroll
    for (int mt = 0; mt < 2; mt++) {
        #pragma unroll
        for (int nt = 0; nt < 8; nt++) {
            int r0  = rowBase + wm * 32 + mt * 16 + gid;
            int r1  = r0 + 8;
            int col = colBase + wn * 64 + nt * 8 + 2 * tig;
            int wc  = col >> 1;
            float* a4 = acc[mt][nt];
            if (MODE == 0) {
                if (r0 < M) CQ[(size_t)r0 * 128 + wc] = pack_f16(a4[0], a4[1]);
                if (r1 < M) CQ[(size_t)r1 * 128 + wc] = pack_f16(a4[2], a4[3]);
            } else if (MODE == 1) {
                float2 bs = *reinterpret_cast<const float2*>(bias + col);
                float2 ba = *reinterpret_cast<const float2*>(bagg + col);
                if (r0 < M) {
                    float2 ag = unpack_f16(aggQ[(size_t)r0 * 128 + wc]);
                    CQ[(size_t)r0 * 128 + wc] = pack_f16(
                        frelu(a4[0] + bs.x) + frelu(ag.x + ba.x),
                        frelu(a4[1] + bs.y) + frelu(ag.y + ba.y));
                }
                if (r1 < M) {
                    float2 ag = unpack_f16(aggQ[(size_t)r1 * 128 + wc]);
                    CQ[(size_t)r1 * 128 + wc] = pack_f16(
                        frelu(a4[2] + bs.x) + frelu(ag.x + ba.x),
                        frelu(a4[3] + bs.y) + frelu(ag.y + ba.y));
                }
            } else {
                float2 bs = *reinterpret_cast<const float2*>(bias + col);
                if (r0 < M)
                    CQ[(size_t)r0 * 128 + wc] = pack_f16(frelu(a4[0] + bs.x),
                                                         frelu(a4[1] + bs.y));
                if (r1 < M)
                    CQ[(size_t)r1 * 128 + wc] = pack_f16(frelu(a4[2] + bs.x),
                                                         frelu(a4[3] + bs.y));
            }
        }
    }
}

// ---------------------------------------------------------------------------
// Fused conversion: node features (both branches) + all 6 weights -> fp16.
// ---------------------------------------------------------------------------
#define CONV_NF_WORDS (2 * (size_t)NW)          // 12.8M words
#define CONV_W_WORDS  (6 * 128 * 256)           // 196608 words

__global__ __launch_bounds__(256)
void conv_all(const float* __restrict__ n1, const float* __restrict__ n2,
              const float* __restrict__ m0, const float* __restrict__ m1,
              const float* __restrict__ m2, const float* __restrict__ m3,
              const float* __restrict__ m4, const float* __restrict__ m5,
              uint32_t* __restrict__ Q, uint32_t* __restrict__ WQ)
{
    size_t idx = (size_t)blockIdx.x * blockDim.x + threadIdx.x;
    if (idx < CONV_NF_WORDS) {
        int br = idx >= (size_t)NW;
        size_t w = idx - (size_t)br * NW;
        const float* nf = br ? n2 : n1;
        float2 v = *reinterpret_cast<const float2*>(nf + w * 2);
        Q[idx] = pack_f16(v.x, v.y);
    } else {
        size_t widx = idx - CONV_NF_WORDS;
        if (widx >= (size_t)CONV_W_WORDS) return;
        int m    = (int)(widx >> 15);
        int rest = (int)(widx & 32767);
        int k2   = rest >> 8;
        int n    = rest & 255;
        const float* Wm = (m == 0) ? m0 : (m == 1) ? m1 : (m == 2) ? m2
                        : (m == 3) ? m3 : (m == 4) ? m4 : m5;
        float a = Wm[(size_t)(2 * k2) * 256 + n];
        float b = Wm[(size_t)(2 * k2 + 1) * 256 + n];
        WQ[widx] = pack_f16(a, b);
    }
}

// ---------------------------------------------------------------------------
// CSR build, both branches
// ---------------------------------------------------------------------------
__global__ void hist_kernel(const int* __restrict__ dst1, const int* __restrict__ dst2,
                            int* __restrict__ deg)
{
    int idx = blockIdx.x * blockDim.x + threadIdx.x;
    if (idx < 2 * N_EDGES) {
        int br = idx >= N_EDGES;
        int e  = idx - br * N_EDGES;
        int d  = br ? dst2[e] : dst1[e];
        atomicAdd(&deg[br * N_NODES + d], 1);
    }
}

__global__ __launch_bounds__(256)
void scan1_kernel(const int* __restrict__ degAll, int* __restrict__ rowstartAll,
                  int* __restrict__ bsums)
{
    __shared__ int wsum[8];
    int br  = blockIdx.x / SCAN_BLKS;
    int blk = blockIdx.x % SCAN_BLKS;
    int t = threadIdx.x, lane = t & 31, w = t >> 5;
    const int* deg = degAll + br * N_NODES;
    int* rowstart  = rowstartAll + br * (N_NODES + 1);

    int base = blk * SCAN_CHUNK + t * 4;
    int v[4];
    #pragma unroll
    for (int i = 0; i < 4; i++)
        v[i] = (base + i < N_NODES) ? deg[base + i] : 0;
    int s = v[0] + v[1] + v[2] + v[3];

    int x = s;
    #pragma unroll
    for (int o = 1; o < 32; o <<= 1) {
        int n = __shfl_up_sync(0xFFFFFFFFu, x, o);
        if (lane >= o) x += n;
    }
    if (lane == 31) wsum[w] = x;
    __syncthreads();
    if (w == 0 && lane < 8) {
        int y = wsum[lane];
        #pragma unroll
        for (int o = 1; o < 8; o <<= 1) {
            int n = __shfl_up_sync(0xFFu, y, o);
            if (lane >= o) y += n;
        }
        wsum[lane] = y;
    }
    __syncthreads();
    int excl = x - s + (w > 0 ? wsum[w - 1] : 0);

    int run = excl;
    #pragma unroll
    for (int i = 0; i < 4; i++) {
        if (base + i < N_NODES) rowstart[base + i] = run;
        run += v[i];
    }
    if (t == 255) bsums[br * SCAN_BLKS + blk] = wsum[7];
}

__global__ __launch_bounds__(256)
void scan2_kernel(const int* __restrict__ bsums, int* __restrict__ rowstartAll,
                  int* __restrict__ cursorAll)
{
    __shared__ int soff;
    int br  = blockIdx.x / SCAN_BLKS;
    int blk = blockIdx.x % SCAN_BLKS;
    int t = threadIdx.x;
    int* rowstart = rowstartAll + br * (N_NODES + 1);
    int* cursor   = cursorAll   + br * N_NODES;

    if (t == 0) {
        int off = 0;
        for (int j = 0; j < blk; j++) off += bsums[br * SCAN_BLKS + j];
        soff = off;
        if (blockIdx.x == 0) {
            rowstartAll[N_NODES] = N_EDGES;
            rowstartAll[(N_NODES + 1) + N_NODES] = N_EDGES;
        }
    }
    __syncthreads();
    int off = soff;
    int base = blk * SCAN_CHUNK + t * 4;
    #pragma unroll
    for (int i = 0; i < 4; i++) {
        int g = base + i;
        if (g < N_NODES) {
            int val = rowstart[g] + off;
            rowstart[g] = val;
            cursor[g]   = val;
        }
    }
}

__global__ void fill_kernel(const int* __restrict__ src1, const int* __restrict__ dst1,
                            const int* __restrict__ src2, const int* __restrict__ dst2,
                            int* __restrict__ cursorAll, int* __restrict__ csrAll)
{
    int idx = blockIdx.x * blockDim.x + threadIdx.x;
    if (idx < 2 * N_EDGES) {
        int br = idx >= N_EDGES;
        int e  = idx - br * N_EDGES;
        int d  = br ? dst2[e] : dst1[e];
        int s  = br ? src2[e] : src1[e];
        int p  = atomicAdd(&cursorAll[br * N_NODES + d], 1);
        csrAll[br * N_EDGES + p] = s;
    }
}

// ---------------------------------------------------------------------------
// Warp-per-node gather of fp16-packed features, both branches.
// ---------------------------------------------------------------------------
__global__ __launch_bounds__(256)
void gather_both(const uint32_t* __restrict__ nfQAll,
                 const int* __restrict__ rowstartAll,
                 const int* __restrict__ csrAll,
                 uint32_t* __restrict__ aggQAll)
{
    int gn = (blockIdx.x * blockDim.x + threadIdx.x) >> 5;
    int lane = threadIdx.x & 31;
    if (gn >= 2 * N_NODES) return;
    int br   = gn >= N_NODES;
    int node = gn - br * N_NODES;
    const uint32_t* nfQ = nfQAll + (size_t)br * NW;
    const int* rowstart = rowstartAll + br * (N_NODES + 1);
    const int* csr      = csrAll + (size_t)br * N_EDGES;
    uint32_t* aggQ      = aggQAll + (size_t)br * NW;

    int beg = rowstart[node], end = rowstart[node + 1];
    float a[8];
    #pragma unroll
    for (int i = 0; i < 8; i++) a[i] = 0.f;
    float b[8];
    #pragma unroll
    for (int i = 0; i < 8; i++) b[i] = 0.f;

    int e = beg;
    for (; e + 1 < end; e += 2) {
        uint4 u = reinterpret_cast<const uint4*>(nfQ + (size_t)csr[e]     * 128)[lane];
        uint4 v = reinterpret_cast<const uint4*>(nfQ + (size_t)csr[e + 1] * 128)[lane];
        float2 f;
        f = unpack_f16(u.x); a[0] += f.x; a[1] += f.y;
        f = unpack_f16(u.y); a[2] += f.x; a[3] += f.y;
        f = unpack_f16(u.z); a[4] += f.x; a[5] += f.y;
        f = unpack_f16(u.w); a[6] += f.x; a[7] += f.y;
        f = unpack_f16(v.x); b[0] += f.x; b[1] += f.y;
        f = unpack_f16(v.y); b[2] += f.x; b[3] += f.y;
        f = unpack_f16(v.z); b[4] += f.x; b[5] += f.y;
        f = unpack_f16(v.w); b[6] += f.x; b[7] += f.y;
    }
    if (e < end) {
        uint4 u = reinterpret_cast<const uint4*>(nfQ + (size_t)csr[e] * 128)[lane];
        float2 f;
        f = unpack_f16(u.x); a[0] += f.x; a[1] += f.y;
        f = unpack_f16(u.y); a[2] += f.x; a[3] += f.y;
        f = unpack_f16(u.z); a[4] += f.x; a[5] += f.y;
        f = unpack_f16(u.w); a[6] += f.x; a[7] += f.y;
    }
    #pragma unroll
    for (int i = 0; i < 8; i++) a[i] += b[i];

    uint4 o;
    o.x = pack_f16(a[0], a[1]);
    o.y = pack_f16(a[2], a[3]);
    o.z = pack_f16(a[4], a[5]);
    o.w = pack_f16(a[6], a[7]);
    reinterpret_cast<uint4*>(aggQ + (size_t)node * 128)[lane] = o;
}

// ---------------------------------------------------------------------------
// Segment sum over fp16-packed h2 (sorted gid), both branches.
// 128 threads = 128 word-cols.
// ---------------------------------------------------------------------------
__global__ __launch_bounds__(128)
void segsum_both(const uint32_t* __restrict__ h2QAll, const int* __restrict__ gid1,
                 const int* __restrict__ gid2,
                 float* __restrict__ TAll, int* __restrict__ countsAll)
{
    __shared__ int sb, se;
    int bidx = blockIdx.x;
    int br   = bidx >> 9;
    int g    = bidx & 511;
    const int* gid = br ? gid2 : gid1;
    const uint32_t* h2Q = h2QAll + (size_t)br * NW;
    if (threadIdx.x == 0) {
        int lo = 0, hi = N_NODES;
        while (lo < hi) { int m = (lo + hi) >> 1; if (gid[m] < g) lo = m + 1; else hi = m; }
        sb = lo;
        lo = sb; hi = N_NODES;
        while (lo < hi) { int m = (lo + hi) >> 1; if (gid[m] < g + 1) lo = m + 1; else hi = m; }
        se = lo;
        countsAll[br * N_GRAPHS + g] = se - sb;
    }
    __syncthreads();
    int beg = sb, end = se, wc = threadIdx.x;
    float sx = 0.f, sy = 0.f;
    for (int r = beg; r < end; r++) {
        float2 f = unpack_f16(h2Q[(size_t)r * 128 + wc]);
        sx += f.x; sy += f.y;
    }
    *reinterpret_cast<float2*>(TAll + ((size_t)br * N_GRAPHS + g) * DFEAT + 2 * wc) =
        make_float2(sx, sy);
}

// ---------------------------------------------------------------------------
// Fused readout + predictor
// ---------------------------------------------------------------------------
__global__ __launch_bounds__(256)
void readout_final(const float* __restrict__ TAll, const int* __restrict__ countsAll,
                   const float* __restrict__ Ro1, const float* __restrict__ rbo1,
                   const float* __restrict__ Ro2, const float* __restrict__ rbo2,
                   const float* __restrict__ Wp, const float* __restrict__ bp,
                   float* __restrict__ out)
{
    __shared__ float ts1[DFEAT], ts2[DFEAT];
    __shared__ float red[256];
    int g = blockIdx.x;
    int t = threadIdx.x;
    ts1[t] = TAll[(size_t)g * DFEAT + t];
    ts2[t] = TAll[((size_t)N_GRAPHS + g) * DFEAT + t];
    __syncthreads();
    float c1 = (float)countsAll[g];
    float c2 = (float)countsAll[N_GRAPHS + g];
    float partial = 0.f;
    if (t < G_FEAT) {
        float s = c1 * rbo1[t] + c2 * rbo2[t];
        #pragma unroll 8
        for (int k = 0; k < DFEAT; k++)
            s += ts1[k] * Ro1[(size_t)k * G_FEAT + t]
               + ts2[k] * Ro2[(size_t)k * G_FEAT + t];
        partial = s * Wp[t];
    }
    red[t] = partial;
    __syncthreads();
    #pragma unroll
    for (int st = 128; st > 0; st >>= 1) {
        if (t < st) red[t] += red[t + st];
        __syncthreads();
    }
    if (t == 0) out[g] = red[0] + bp[0];
}

// ---------------------------------------------------------------------------
extern "C" void kernel_launch(void* const* d_in, const int* in_sizes, int n_in,
                              void* d_out, int out_size)
{
    const float* nf1 = (const float*)d_in[0];
    const float* nf2 = (const float*)d_in[2];
    const int* src1 = (const int*)d_in[4];
    const int* dst1 = (const int*)d_in[5];
    const int* gid1 = (const int*)d_in[6];
    const int* src2 = (const int*)d_in[7];
    const int* dst2 = (const int*)d_in[8];
    const int* gid2 = (const int*)d_in[9];
    const float* W1  = (const float*)d_in[10]; const float* b1  = (const float*)d_in[11];
    const float* Wr1 = (const float*)d_in[12]; const float* br1 = (const float*)d_in[13];
    const float* W2  = (const float*)d_in[14]; const float* b2  = (const float*)d_in[15];
    const float* Wr2 = (const float*)d_in[16]; const float* br2 = (const float*)d_in[17];
    const float* Ri1 = (const float*)d_in[18]; const float* rbi1 = (const float*)d_in[19];
    const float* Ro1 = (const float*)d_in[20]; const float* rbo1 = (const float*)d_in[21];
    const float* Ri2 = (const float*)d_in[22]; const float* rbi2 = (const float*)d_in[23];
    const float* Ro2 = (const float*)d_in[24]; const float* rbo2 = (const float*)d_in[25];
    const float* Wp  = (const float*)d_in[26]; const float* bp   = (const float*)d_in[27];

    float *T;
    uint32_t *t2Q, *aggQ, *nfQ, *h1Q, *WQ;
    int *counts, *deg, *rowstart, *cursor, *csr_src, *bsums;
    cudaGetSymbolAddress((void**)&t2Q,      g_t2Q);
    cudaGetSymbolAddress((void**)&aggQ,     g_aggQ);
    cudaGetSymbolAddress((void**)&nfQ,      g_nfQ);
    cudaGetSymbolAddress((void**)&h1Q,      g_h1Q);
    cudaGetSymbolAddress((void**)&WQ,       g_WQ);
    cudaGetSymbolAddress((void**)&T,        g_T);
    cudaGetSymbolAddress((void**)&counts,   g_counts);
    cudaGetSymbolAddress((void**)&deg,      g_deg);
    cudaGetSymbolAddress((void**)&rowstart, g_rowstart);
    cudaGetSymbolAddress((void**)&cursor,   g_cursor);
    cudaGetSymbolAddress((void**)&csr_src,  g_csr_src);
    cudaGetSymbolAddress((void**)&bsums,    g_bsums);

    cudaFuncSetAttribute(gemm_mma<0>, cudaFuncAttributeMaxDynamicSharedMemorySize, SMEM_BYTES);
    cudaFuncSetAttribute(gemm_mma<1>, cudaFuncAttributeMaxDynamicSharedMemorySize, SMEM_BYTES);
    cudaFuncSetAttribute(gemm_mma<2>, cudaFuncAttributeMaxDynamicSharedMemorySize, SMEM_BYTES);

    static cudaStream_t s_s2 = nullptr;
    static cudaEvent_t  s_evF = nullptr, s_evNF = nullptr, s_evG = nullptr;
    static bool s_tried = false;
    if (!s_tried) {
        s_tried = true;
        bool ok =
            cudaStreamCreateWithFlags(&s_s2, cudaStreamNonBlocking) == cudaSuccess &&
            cudaEventCreateWithFlags(&s_evF,  cudaEventDisableTiming) == cudaSuccess &&
            cudaEventCreateWithFlags(&s_evNF, cudaEventDisableTiming) == cudaSuccess &&
            cudaEventCreateWithFlags(&s_evG,  cudaEventDisableTiming) == cudaSuccess;
        if (!ok) s_s2 = nullptr;
    }
    const bool par = (s_s2 != nullptr);
    cudaStream_t s0 = (cudaStream_t)0;
    cudaStream_t s2 = par ? s_s2 : s0;

    uint32_t* t2Q1 = t2Q;   uint32_t* t2Q2 = t2Q + (size_t)NW;
    uint32_t* aggQ1 = aggQ; uint32_t* aggQ2 = aggQ + (size_t)NW;
    uint32_t* nfQ1 = nfQ;   uint32_t* nfQ2 = nfQ + (size_t)NW;
    uint32_t* h1Q1 = h1Q;   uint32_t* h1Q2 = h1Q + (size_t)NW;
    const int WSZ = 128 * 256;   // slots: 0=W1 1=Wr1 2=Ri1 3=W2 4=Wr2 5=Ri2

    dim3 gemm_grid((N_NODES + 127) / 128, 2, 2);    // 391 x 2 x 2 (both branches)
    int eb2 = (2 * N_EDGES + 255) / 256;
    int gat_blocks = (2 * N_NODES * 32 + 255) / 256;
    size_t conv_items = CONV_NF_WORDS + CONV_W_WORDS;

    // ---- fork ----
    if (par) {
        cudaEventRecord(s_evF, s0);
        cudaStreamWaitEvent(s_s2, s_evF, 0);
    }

    // s0: fused conversion (features + weights)
    conv_all<<<(int)((conv_items + 255) / 256), 256, 0, s0>>>(
        nf1, nf2, W1, Wr1, Ri1, W2, Wr2, Ri2, nfQ, WQ);
    if (par) cudaEventRecord(s_evNF, s0);

    // s2: CSR chain, then combined gather (waits conv for nfQ)
    cudaMemsetAsync(deg, 0, 2 * N_NODES * sizeof(int), s2);
    hist_kernel<<<eb2, 256, 0, s2>>>(dst1, dst2, deg);
    scan1_kernel<<<2 * SCAN_BLKS, 256, 0, s2>>>(deg, rowstart, bsums);
    scan2_kernel<<<2 * SCAN_BLKS, 256, 0, s2>>>(bsums, rowstart, cursor);
    fill_kernel<<<eb2, 256, 0, s2>>>(src1, dst1, src2, dst2, cursor, csr_src);
    if (par) cudaStreamWaitEvent(s_s2, s_evNF, 0);
    gather_both<<<gat_blocks, 256, 0, s2>>>(nfQ, rowstart, csr_src, aggQ);
    if (par) cudaEventRecord(s_evG, s_s2);

    // s0: t2 = h @ Wr (both branches) — overlaps CSR+gather
    gemm_mma<0><<<gemm_grid, 256, SMEM_BYTES, s0>>>(
        nfQ1, nfQ2, WQ + 1 * WSZ, WQ + 4 * WSZ,
        nullptr, nullptr, nullptr, nullptr, nullptr, nullptr,
        t2Q1, t2Q2, N_NODES);
    // h1 = relu(hagg@W + b) + relu(t2 + br)
    if (par) cudaStreamWaitEvent(s0, s_evG, 0);
    gemm_mma<1><<<gemm_grid, 256, SMEM_BYTES, s0>>>(
        aggQ1, aggQ2, WQ + 0 * WSZ, WQ + 3 * WSZ,
        b1, b2, t2Q1, t2Q2, br1, br2,
        h1Q1, h1Q2, N_NODES);
    // h2 = relu(h1@Ri + rbi)  (overwrite t2Q)
    gemm_mma<2><<<gemm_grid, 256, SMEM_BYTES, s0>>>(
        h1Q1, h1Q2, WQ + 2 * WSZ, WQ + 5 * WSZ,
        rbi1, rbi2, nullptr, nullptr, nullptr, nullptr,
        t2Q1, t2Q2, N_NODES);
    // T[g] = segsum h2 (both branches)
    segsum_both<<<2 * N_GRAPHS, 128, 0, s0>>>(t2Q, gid1, gid2, T, counts);
    // fused readout + predictor
    readout_final<<<N_GRAPHS, 256, 0, s0>>>(T, counts, Ro1, rbo1, Ro2, rbo2, Wp, bp,
                                            (float*)d_out);
}